// round 1
// baseline (speedup 1.0000x reference)
#include <cuda_runtime.h>
#include <math.h>
#include <stdint.h>

#define NB      2
#define LQ      8192
#define LEN_IN  149760
#define DM      256
#define NHEADS  8
#define NLEV    4
#define NPTS    4
#define DHEAD   32

// ---------------- scratch (device globals; no cudaMalloc allowed) ----------
__device__ float g_value[(size_t)NB * LEN_IN * DM];                       // 306 MB
__device__ float g_off  [(size_t)NB * LQ * (NHEADS * NLEV * NPTS * 3)];  // 25 MB
__device__ float g_attn [(size_t)NB * LQ * (NHEADS * NLEV * NPTS)];      // 8 MB
__device__ float g_mid  [(size_t)NB * LQ * DM];                          // 16 MB

// ---------------- generic fp32 GEMM: C = A(MxK) * B(KxN) + bias -----------
// BM=BN=128, BK=8, 256 threads, 8x8 register tile per thread.
// Requires M%128==0, N%128==0, K%8==0 (true for all 4 GEMMs here).
__global__ __launch_bounds__(256) void sgemm_bias_kernel(
    const float* __restrict__ A, const float* __restrict__ B,
    const float* __restrict__ bias, float* __restrict__ C,
    int M, int N, int K)
{
    const int BM = 128, BN = 128, BK = 8;
    __shared__ float As[BK][BM];
    __shared__ float Bs[BK][BN];

    const int tid = threadIdx.x;
    const int bm = blockIdx.y, bn = blockIdx.x;

    const float* Ab = A + (size_t)bm * BM * K;
    const float* Bb = B + (size_t)bn * BN;

    const int aRow = tid >> 1;            // 0..127
    const int aCol = (tid & 1) * 4;       // 0 or 4
    const int bRow = tid >> 5;            // 0..7
    const int bCol = (tid & 31) * 4;      // 0..124

    const int ty = tid >> 4;              // 0..15
    const int tx = tid & 15;              // 0..15

    float acc[8][8];
#pragma unroll
    for (int i = 0; i < 8; i++)
#pragma unroll
        for (int j = 0; j < 8; j++) acc[i][j] = 0.f;

    for (int k0 = 0; k0 < K; k0 += BK) {
        float4 av = *(const float4*)(Ab + (size_t)aRow * K + k0 + aCol);
        As[aCol + 0][aRow] = av.x;
        As[aCol + 1][aRow] = av.y;
        As[aCol + 2][aRow] = av.z;
        As[aCol + 3][aRow] = av.w;

        float4 bv4 = *(const float4*)(Bb + (size_t)(k0 + bRow) * N + bCol);
        *(float4*)(&Bs[bRow][bCol]) = bv4;

        __syncthreads();

#pragma unroll
        for (int kk = 0; kk < BK; kk++) {
            float regA[8], regB[8];
            float4 a0 = *(const float4*)(&As[kk][ty * 8 + 0]);
            float4 a1 = *(const float4*)(&As[kk][ty * 8 + 4]);
            regA[0]=a0.x; regA[1]=a0.y; regA[2]=a0.z; regA[3]=a0.w;
            regA[4]=a1.x; regA[5]=a1.y; regA[6]=a1.z; regA[7]=a1.w;
            float4 b0 = *(const float4*)(&Bs[kk][tx * 8 + 0]);
            float4 b1 = *(const float4*)(&Bs[kk][tx * 8 + 4]);
            regB[0]=b0.x; regB[1]=b0.y; regB[2]=b0.z; regB[3]=b0.w;
            regB[4]=b1.x; regB[5]=b1.y; regB[6]=b1.z; regB[7]=b1.w;
#pragma unroll
            for (int i = 0; i < 8; i++)
#pragma unroll
                for (int j = 0; j < 8; j++)
                    acc[i][j] = fmaf(regA[i], regB[j], acc[i][j]);
        }
        __syncthreads();
    }

    // epilogue: add bias, store (two float4 per row)
    const int colBase = bn * BN + tx * 8;
    float bvv[8];
#pragma unroll
    for (int j = 0; j < 8; j++) bvv[j] = bias[colBase + j];

#pragma unroll
    for (int i = 0; i < 8; i++) {
        int row = bm * BM + ty * 8 + i;
        float4 o0, o1;
        o0.x = acc[i][0] + bvv[0]; o0.y = acc[i][1] + bvv[1];
        o0.z = acc[i][2] + bvv[2]; o0.w = acc[i][3] + bvv[3];
        o1.x = acc[i][4] + bvv[4]; o1.y = acc[i][5] + bvv[5];
        o1.z = acc[i][6] + bvv[6]; o1.w = acc[i][7] + bvv[7];
        *(float4*)(&C[(size_t)row * N + colBase + 0]) = o0;
        *(float4*)(&C[(size_t)row * N + colBase + 4]) = o1;
    }
}

// ---------------- softmax over 16 contiguous elements per row -------------
__global__ void softmax16_kernel(float* __restrict__ a, int rows)
{
    int r = blockIdx.x * blockDim.x + threadIdx.x;
    if (r >= rows) return;
    float* p = a + (size_t)r * 16;
    float v[16];
    float m = -1e30f;
#pragma unroll
    for (int i = 0; i < 16; i++) { v[i] = p[i]; m = fmaxf(m, v[i]); }
    float s = 0.f;
#pragma unroll
    for (int i = 0; i < 16; i++) { v[i] = __expf(v[i] - m); s += v[i]; }
    float inv = 1.f / s;
#pragma unroll
    for (int i = 0; i < 16; i++) p[i] = v[i] * inv;
}

// ---------------- trilinear deformable sampling ----------------------------
// grid = NB*LQ blocks; block = 256 threads = 8 warps (one per head);
// lane = channel within head. Each corner gather is a single 128B line.
__global__ __launch_bounds__(256) void sample_kernel(
    const float* __restrict__ rp,      // (NB, LQ, NLEV, 3)
    const int*   __restrict__ shapes,  // (NLEV, 3) = D,H,W
    const int*   __restrict__ starts)  // (NLEV,)
{
    const int q    = blockIdx.x;          // n*LQ + lq
    const int h    = threadIdx.x >> 5;
    const int lane = threadIdx.x & 31;

    __shared__ float s_rp[NLEV * 3];
    __shared__ int   s_dim[NLEV * 3];
    __shared__ int   s_start[NLEV];
    if (threadIdx.x < NLEV * 3) {
        s_rp[threadIdx.x]  = rp[(size_t)q * (NLEV * 3) + threadIdx.x];
        s_dim[threadIdx.x] = shapes[threadIdx.x];
    }
    if (threadIdx.x < NLEV) s_start[threadIdx.x] = starts[threadIdx.x];
    __syncthreads();

    const int n = q / LQ;
    const float* offq = g_off  + (size_t)q * (NHEADS * NLEV * NPTS * 3) + h * (NLEV * NPTS * 3);
    const float* attq = g_attn + (size_t)q * (NHEADS * NLEV * NPTS)     + h * (NLEV * NPTS);

    float acc = 0.f;

#pragma unroll
    for (int l = 0; l < NLEV; l++) {
        const int D = s_dim[l * 3 + 0];
        const int H = s_dim[l * 3 + 1];
        const int W = s_dim[l * 3 + 2];
        const float fD = (float)D, fH = (float)H, fW = (float)W;
        const float* vbase = g_value
            + ((size_t)(n * LEN_IN + s_start[l])) * DM + h * DHEAD + lane;
        const float rx = s_rp[l * 3 + 0];
        const float ry = s_rp[l * 3 + 1];
        const float rz = s_rp[l * 3 + 2];

#pragma unroll
        for (int p = 0; p < NPTS; p++) {
            const int o = l * NPTS + p;
            const float a  = attq[o];
            const float x = (rx + offq[o * 3 + 0] / fW) * fW - 0.5f;
            const float y = (ry + offq[o * 3 + 1] / fH) * fH - 0.5f;
            const float z = (rz + offq[o * 3 + 2] / fD) * fD - 0.5f;

            const float x0f = floorf(x), y0f = floorf(y), z0f = floorf(z);
            const int   x0 = (int)x0f,   y0 = (int)y0f,   z0 = (int)z0f;
            const float fx = x - x0f,    fy = y - y0f,    fz = z - z0f;

#pragma unroll
            for (int c = 0; c < 8; c++) {
                const int dx = c & 1, dy = (c >> 1) & 1, dz = (c >> 2) & 1;
                const int xi = x0 + dx, yi = y0 + dy, zi = z0 + dz;
                const float w = (dx ? fx : 1.f - fx)
                              * (dy ? fy : 1.f - fy)
                              * (dz ? fz : 1.f - fz);
                if (xi >= 0 && xi < W && yi >= 0 && yi < H &&
                    zi >= 0 && zi < D && w != 0.f) {
                    const size_t idx = ((size_t)zi * H + yi) * W + xi;
                    acc = fmaf(a * w, vbase[idx * DM], acc);
                }
            }
        }
    }

    g_mid[(size_t)q * DM + h * DHEAD + lane] = acc;
}

// ---------------------------------------------------------------------------
extern "C" void kernel_launch(void* const* d_in, const int* in_sizes, int n_in,
                              void* d_out, int out_size)
{
    const float* query  = (const float*)d_in[0];
    const float* refp   = (const float*)d_in[1];
    const float* inp    = (const float*)d_in[2];
    const int*   shapes = (const int*)  d_in[3];
    const int*   starts = (const int*)  d_in[4];
    const float* Wv     = (const float*)d_in[5];
    const float* bv     = (const float*)d_in[6];
    const float* Woff   = (const float*)d_in[7];
    const float* boff   = (const float*)d_in[8];
    const float* Wattn  = (const float*)d_in[9];
    const float* battn  = (const float*)d_in[10];
    const float* Wout   = (const float*)d_in[11];
    const float* bout   = (const float*)d_in[12];
    float* out = (float*)d_out;

    float *pv, *po, *pa, *pm;
    cudaGetSymbolAddress((void**)&pv, g_value);
    cudaGetSymbolAddress((void**)&po, g_off);
    cudaGetSymbolAddress((void**)&pa, g_attn);
    cudaGetSymbolAddress((void**)&pm, g_mid);

    dim3 blk(256);

    // 1) value = input_flatten @ Wv + bv      (299520 x 256 x 256)
    {
        dim3 grid(DM / 128, (NB * LEN_IN) / 128);
        sgemm_bias_kernel<<<grid, blk>>>(inp, Wv, bv, pv, NB * LEN_IN, DM, DM);
    }
    // 2) off = query @ Woff + boff            (16384 x 384 x 256)
    {
        dim3 grid(384 / 128, (NB * LQ) / 128);
        sgemm_bias_kernel<<<grid, blk>>>(query, Woff, boff, po, NB * LQ, 384, DM);
    }
    // 3) attn logits = query @ Wattn + battn  (16384 x 128 x 256)
    {
        dim3 grid(128 / 128, (NB * LQ) / 128);
        sgemm_bias_kernel<<<grid, blk>>>(query, Wattn, battn, pa, NB * LQ, 128, DM);
    }
    // 4) softmax over 16 (levels*points) per (n,q,head)
    softmax16_kernel<<<(NB * LQ * NHEADS + 255) / 256, 256>>>(pa, NB * LQ * NHEADS);

    // 5) deformable trilinear sampling -> g_mid
    sample_kernel<<<NB * LQ, 256>>>(refp, shapes, starts);

    // 6) out = g_mid @ Wout + bout            (16384 x 256 x 256)
    {
        dim3 grid(DM / 128, (NB * LQ) / 128);
        sgemm_bias_kernel<<<grid, blk>>>(pm, Wout, bout, out, NB * LQ, DM, DM);
    }
}